// round 3
// baseline (speedup 1.0000x reference)
#include <cuda_runtime.h>
#include <cuda_bf16.h>

#define GRID 8192   // one block per row

__device__ float        g_partials[GRID];
__device__ unsigned int g_done = 0;

// softplus(x) = max(x,0) + log1p(exp(-|x|)); log1p via A&S 4.1.43 poly (|err|<=1e-5 on [0,1])
__device__ __forceinline__ float softplus_fast(float x) {
    float y = exp2f(fabsf(x) * -1.4426950408889634f);   // exp(-|x|), 1 MUFU
    float p = y * (0.99949556f +
              y * (-0.49190896f +
              y * (0.28947478f +
              y * (-0.13606275f +
              y *  0.03215845f))));
    return fmaxf(x, 0.0f) + p;
}

__global__ __launch_bounds__(512, 4) void bce_fused(
    const float* __restrict__ x,
    const int* __restrict__ tg32,     // int64 targets viewed as int pairs (LE low word)
    float* __restrict__ out,
    int N, float inv_count)
{
    const int row = blockIdx.x;
    const int t   = tg32[row * 2];    // low 32 bits of int64 target
    const int q   = t >> 2;           // boundary float4 index
    const int r   = t & 3;

    const float4* __restrict__ xr =
        reinterpret_cast<const float4*>(x + (size_t)row * N);
    const int n4 = N >> 2;

    float s = 0.0f;

    if (n4 == 2048) {
        #pragma unroll
        for (int k = 0; k < 4; k++) {
            const int idx = threadIdx.x + (k << 9);
            float4 v = xr[idx];
            s += softplus_fast(v.x) + softplus_fast(v.y)
               + softplus_fast(v.z) + softplus_fast(v.w);
            if (idx < q) {
                s -= (v.x + v.y) + (v.z + v.w);
            } else if (idx == q) {      // rare: one thread per block
                if (r > 0) s -= v.x;
                if (r > 1) s -= v.y;
                if (r > 2) s -= v.z;
            }
        }
    } else {
        for (int idx = threadIdx.x; idx < n4; idx += blockDim.x) {
            float4 v = xr[idx];
            s += softplus_fast(v.x) + softplus_fast(v.y)
               + softplus_fast(v.z) + softplus_fast(v.w);
            if (idx < q) {
                s -= (v.x + v.y) + (v.z + v.w);
            } else if (idx == q) {
                if (r > 0) s -= v.x;
                if (r > 1) s -= v.y;
                if (r > 2) s -= v.z;
            }
        }
    }

    // ---- block reduction (16 warps, all float) ----
    #pragma unroll
    for (int o = 16; o > 0; o >>= 1)
        s += __shfl_xor_sync(0xFFFFFFFFu, s, o);

    __shared__ float warp_sums[16];
    const int lane = threadIdx.x & 31;
    const int wid  = threadIdx.x >> 5;
    if (lane == 0) warp_sums[wid] = s;
    __syncthreads();

    __shared__ bool is_last;
    if (threadIdx.x < 32) {
        float v = (lane < 16) ? warp_sums[lane] : 0.0f;
        #pragma unroll
        for (int o = 8; o > 0; o >>= 1)
            v += __shfl_xor_sync(0xFFFFFFFFu, v, o);
        if (lane == 0) {
            g_partials[blockIdx.x] = v;
            __threadfence();
            unsigned int ticket = atomicAdd(&g_done, 1u);
            is_last = (ticket == gridDim.x - 1);
        }
    }
    __syncthreads();

    // ---- last block: tail reduction over GRID partials ----
    if (is_last) {
        float d = 0.0f;
        for (int i = threadIdx.x; i < GRID; i += 512)
            d += g_partials[i];

        #pragma unroll
        for (int o = 16; o > 0; o >>= 1)
            d += __shfl_xor_sync(0xFFFFFFFFu, d, o);

        if (lane == 0) warp_sums[wid] = d;
        __syncthreads();

        if (threadIdx.x < 32) {
            float v = (lane < 16) ? warp_sums[lane] : 0.0f;
            #pragma unroll
            for (int o = 8; o > 0; o >>= 1)
                v += __shfl_xor_sync(0xFFFFFFFFu, v, o);
            if (lane == 0) {
                out[0] = v * inv_count;
                g_done = 0;   // reset for next graph replay
            }
        }
    }
}

extern "C" void kernel_launch(void* const* d_in, const int* in_sizes, int n_in,
                              void* d_out, int out_size)
{
    const float* x    = (const float*)d_in[0];
    const int*   tg32 = (const int*)d_in[1];   // int64 viewed as int pairs
    float* out = (float*)d_out;

    const int B = in_sizes[1];
    const int N = in_sizes[0] / B;

    const float inv_count = (float)(1.0 / ((double)B * (double)N));
    bce_fused<<<B, 512>>>(x, tg32, out, N, inv_count);
}